// round 1
// baseline (speedup 1.0000x reference)
#include <cuda_runtime.h>

#define HH 200
#define WW 320
#define CC 256
#define HWSZ (HH * WW)
#define RS 14
#define BINS (RS * RS)

// Scratch: transposed feature [H][W][C] (65.5 MB) + 196 bin maxima (ordered-uint encoded)
__device__ __align__(128) static float g_featT[HWSZ * CC];
__device__ static unsigned g_bins[BINS];

// Monotonic float <-> uint encoding so atomicMax on unsigned == float max
__device__ __forceinline__ unsigned enc_f(float f) {
    unsigned u = __float_as_uint(f);
    return (u & 0x80000000u) ? ~u : (u | 0x80000000u);
}
__device__ __forceinline__ float dec_f(unsigned u) {
    return __uint_as_float((u & 0x80000000u) ? (u ^ 0x80000000u) : ~u);
}

__global__ void init_bins_kernel() {
    int t = threadIdx.x;
    if (t < BINS) g_bins[t] = 0u;  // encodes the most-negative value
}

// Transpose feature [C][H*W] -> g_featT [H*W][C], 32x32 tiles in shared.
__global__ void transpose_kernel(const float* __restrict__ A) {
    __shared__ float tile[32][33];
    int x = blockIdx.x * 32 + threadIdx.x;  // position in HW dim
    int y0 = blockIdx.y * 32;               // base in C dim
#pragma unroll
    for (int j = 0; j < 32; j += 8)
        tile[threadIdx.y + j][threadIdx.x] = A[(size_t)(y0 + threadIdx.y + j) * HWSZ + x];
    __syncthreads();
    int outRow = blockIdx.x * 32;           // HW
    int outCol = y0 + threadIdx.x;          // C
#pragma unroll
    for (int j = 0; j < 32; j += 8)
        g_featT[(size_t)(outRow + threadIdx.y + j) * CC + outCol] =
            tile[threadIdx.x][threadIdx.y + j];
}

// One warp per (roi, bin). Lanes sweep channels with float4 loads (coalesced
// 512B per corner per iter). Warp-max -> one atomicMax per warp into g_bins[mn].
__global__ void roi_max_kernel(const float* __restrict__ rois, int R) {
    int warp = threadIdx.x >> 5;
    int lane = threadIdx.x & 31;
    int wid = blockIdx.x * (blockDim.x >> 5) + warp;
    if (wid >= R * BINS) return;
    int r = wid / BINS;
    int mn = wid - r * BINS;
    int m = mn / RS;
    int n = mn - m * RS;

    float r0 = __ldg(rois + 4 * r + 0);
    float r1 = __ldg(rois + 4 * r + 1);
    float r2 = __ldg(rois + 4 * r + 2);
    float r3 = __ldg(rois + 4 * r + 3);
    float sh = (r2 - r0) / (float)RS;
    float sw = (r3 - r1) / (float)RS;
    float yb = r0 + sh * (float)m;
    float xb = r1 + sw * (float)n;
    const float fr0 = 1.0f / 3.0f, fr1 = 2.0f / 3.0f;
    float ys[2] = {yb + sh * fr0, yb + sh * fr1};
    float xs[2] = {xb + sw * fr0, xb + sw * fr1};

    float vmax = __int_as_float(0xff800000);  // -inf

#pragma unroll
    for (int i = 0; i < 2; i++) {
#pragma unroll
        for (int j = 0; j < 2; j++) {
            float y = ys[i], x = xs[j];
            int yf = (int)floorf(y);
            int xf = (int)floorf(x);
            // clamp BEFORE weights are computed (faithful to reference)
            int y1 = min(max(yf, 0), HH - 1);
            int y2 = min(max(yf + 1, 0), HH - 1);
            int x1 = min(max(xf, 0), WW - 1);
            int x2 = min(max(xf + 1, 0), WW - 1);
            float wxl = x - (float)x1;   // toward x2
            float wxh = (float)x2 - x;   // toward x1
            float wyl = y - (float)y1;
            float wyh = (float)y2 - y;

            const float4* p11 = (const float4*)(g_featT + (size_t)(y1 * WW + x1) * CC);
            const float4* p12 = (const float4*)(g_featT + (size_t)(y1 * WW + x2) * CC);
            const float4* p21 = (const float4*)(g_featT + (size_t)(y2 * WW + x1) * CC);
            const float4* p22 = (const float4*)(g_featT + (size_t)(y2 * WW + x2) * CC);

#pragma unroll
            for (int cc = 0; cc < 2; cc++) {
                int idx = cc * 32 + lane;  // 64 float4 covers 256 channels
                float4 a = p11[idx];
                float4 b = p12[idx];
                float4 c = p21[idx];
                float4 d = p22[idx];
                float v0 = (a.x * wxh + b.x * wxl) * wyh + (c.x * wxh + d.x * wxl) * wyl;
                float v1 = (a.y * wxh + b.y * wxl) * wyh + (c.y * wxh + d.y * wxl) * wyl;
                float v2 = (a.z * wxh + b.z * wxl) * wyh + (c.z * wxh + d.z * wxl) * wyl;
                float v3 = (a.w * wxh + b.w * wxl) * wyh + (c.w * wxh + d.w * wxl) * wyl;
                vmax = fmaxf(vmax, fmaxf(fmaxf(v0, v1), fmaxf(v2, v3)));
            }
        }
    }

#pragma unroll
    for (int o = 16; o; o >>= 1)
        vmax = fmaxf(vmax, __shfl_xor_sync(0xffffffffu, vmax, o));
    if (lane == 0) atomicMax(&g_bins[mn], enc_f(vmax));
}

// Broadcast bin_max[196] to out[R][C][14][14] with float4 stores.
// 196 % 4 == 0, so a float4 never straddles the mn wrap.
__global__ void bcast_kernel(float* __restrict__ out, int total4) {
    __shared__ float s[BINS];
    int t = threadIdx.x;
    if (t < BINS) s[t] = dec_f(g_bins[t]);
    __syncthreads();
    int g = blockIdx.x * blockDim.x + t;
    if (g >= total4) return;
    int mn0 = (g * 4) % BINS;
    float4 v = make_float4(s[mn0], s[mn0 + 1], s[mn0 + 2], s[mn0 + 3]);
    ((float4*)out)[g] = v;
}

extern "C" void kernel_launch(void* const* d_in, const int* in_sizes, int n_in,
                              void* d_out, int out_size) {
    const float* feature = (const float*)d_in[0];
    const float* rois = (const float*)d_in[1];
    int R = in_sizes[1] / 4;

    init_bins_kernel<<<1, 256>>>();

    dim3 tb(32, 8);
    dim3 tg(HWSZ / 32, CC / 32);
    transpose_kernel<<<tg, tb>>>(feature);

    int warps = R * BINS;
    int blocks = (warps + 7) / 8;
    roi_max_kernel<<<blocks, 256>>>(rois, R);

    int total4 = out_size / 4;
    bcast_kernel<<<(total4 + 255) / 256, 256>>>((float*)d_out, total4);
}

// round 3
// speedup vs baseline: 1.2884x; 1.2884x over previous
#include <cuda_runtime.h>
#include <cuda_fp16.h>

#define HH 200
#define WW 320
#define CC 256
#define HWSZ (HH * WW)
#define RS 14
#define BINS (RS * RS)

// Scratch: transposed feature [H][W][C] in fp16 (32.8 MB) + 196 bin maxima
__device__ __align__(128) static __half g_featT[(size_t)HWSZ * CC];
__device__ static unsigned g_bins[BINS];

// Monotonic float <-> uint encoding so atomicMax on unsigned == float max
__device__ __forceinline__ unsigned enc_f(float f) {
    unsigned u = __float_as_uint(f);
    return (u & 0x80000000u) ? ~u : (u | 0x80000000u);
}
__device__ __forceinline__ float dec_f(unsigned u) {
    return __uint_as_float((u & 0x80000000u) ? (u ^ 0x80000000u) : ~u);
}

__global__ void init_bins_kernel() {
    int t = threadIdx.x;
    if (t < BINS) g_bins[t] = 0u;  // encodes most-negative float
}

// Transpose feature [C][H*W] fp32 -> g_featT [H*W][C] fp16.
// Tile: 64 channels x 32 hw positions. Stores are half2 (128B/warp coalesced).
__global__ void transpose_kernel(const float* __restrict__ A) {
    __shared__ float tile[64][33];
    int hw0 = blockIdx.x * 32;
    int c0 = blockIdx.y * 64;
    int tx = threadIdx.x, ty = threadIdx.y;  // 32 x 8
#pragma unroll
    for (int j = 0; j < 64; j += 8)
        tile[ty + j][tx] = A[(size_t)(c0 + ty + j) * HWSZ + hw0 + tx];
    __syncthreads();
    // warp ty handles hw rows ty, ty+8, ty+16, ty+24; lane tx = channel pair
#pragma unroll
    for (int rr = 0; rr < 4; rr++) {
        int hwr = ty + rr * 8;
        __half2 h = __floats2half2_rn(tile[2 * tx][hwr], tile[2 * tx + 1][hwr]);
        ((__half2*)(g_featT + (size_t)(hw0 + hwr) * CC + c0))[tx] = h;
    }
}

// One warp per (roi, bin). A corner row is 256 fp16 = 512B = 32 lanes x 16B:
// exactly one LDG.128 per corner per lane. fp32 math after conversion.
__global__ void roi_max_kernel(const float* __restrict__ rois, int R) {
    int warp = threadIdx.x >> 5;
    int lane = threadIdx.x & 31;
    int wid = blockIdx.x * (blockDim.x >> 5) + warp;
    if (wid >= R * BINS) return;
    int r = wid / BINS;
    int mn = wid - r * BINS;
    int m = mn / RS;
    int n = mn - m * RS;

    float r0 = __ldg(rois + 4 * r + 0);
    float r1 = __ldg(rois + 4 * r + 1);
    float r2 = __ldg(rois + 4 * r + 2);
    float r3 = __ldg(rois + 4 * r + 3);
    float sh = (r2 - r0) / (float)RS;
    float sw = (r3 - r1) / (float)RS;
    float yb = r0 + sh * (float)m;
    float xb = r1 + sw * (float)n;
    const float fr0 = 1.0f / 3.0f, fr1 = 2.0f / 3.0f;
    float ys[2] = {yb + sh * fr0, yb + sh * fr1};
    float xs[2] = {xb + sw * fr0, xb + sw * fr1};

    float vmax = __int_as_float(0xff800000);  // -inf

#pragma unroll
    for (int i = 0; i < 2; i++) {
#pragma unroll
        for (int j = 0; j < 2; j++) {
            float y = ys[i], x = xs[j];
            int yf = (int)floorf(y);
            int xf = (int)floorf(x);
            // clamp BEFORE weights (faithful to reference)
            int y1 = min(max(yf, 0), HH - 1);
            int y2 = min(max(yf + 1, 0), HH - 1);
            int x1 = min(max(xf, 0), WW - 1);
            int x2 = min(max(xf + 1, 0), WW - 1);
            float wxl = x - (float)x1;   // toward x2
            float wxh = (float)x2 - x;   // toward x1
            float wyl = y - (float)y1;
            float wyh = (float)y2 - y;

            const uint4* p11 = (const uint4*)(g_featT + (size_t)(y1 * WW + x1) * CC);
            const uint4* p12 = (const uint4*)(g_featT + (size_t)(y1 * WW + x2) * CC);
            const uint4* p21 = (const uint4*)(g_featT + (size_t)(y2 * WW + x1) * CC);
            const uint4* p22 = (const uint4*)(g_featT + (size_t)(y2 * WW + x2) * CC);

            uint4 A = p11[lane];
            uint4 B = p12[lane];
            uint4 C = p21[lane];
            uint4 D = p22[lane];
#pragma unroll
            for (int k = 0; k < 4; k++) {
                float2 fa = __half22float2(*(const __half2*)(&((const unsigned*)&A)[k]));
                float2 fb = __half22float2(*(const __half2*)(&((const unsigned*)&B)[k]));
                float2 fc = __half22float2(*(const __half2*)(&((const unsigned*)&C)[k]));
                float2 fd = __half22float2(*(const __half2*)(&((const unsigned*)&D)[k]));
                float v0 = (fa.x * wxh + fb.x * wxl) * wyh + (fc.x * wxh + fd.x * wxl) * wyl;
                float v1 = (fa.y * wxh + fb.y * wxl) * wyh + (fc.y * wxh + fd.y * wxl) * wyl;
                vmax = fmaxf(vmax, fmaxf(v0, v1));
            }
        }
    }

#pragma unroll
    for (int o = 16; o; o >>= 1)
        vmax = fmaxf(vmax, __shfl_xor_sync(0xffffffffu, vmax, o));
    if (lane == 0) atomicMax(&g_bins[mn], enc_f(vmax));
}

// Broadcast bin_max[196] to out[R][C][14][14]; grid-stride, float4 stores,
// 49-entry float4 table in shared (196 % 4 == 0 so no straddle).
__global__ void bcast_kernel(float* __restrict__ out, int total4) {
    __shared__ float4 s4[49];
    int t = threadIdx.x;
    if (t < BINS) ((float*)s4)[t] = dec_f(g_bins[t]);
    __syncthreads();
    int stride = blockDim.x * gridDim.x;
    for (int g = blockIdx.x * blockDim.x + t; g < total4; g += stride)
        ((float4*)out)[g] = s4[g % 49];
}

extern "C" void kernel_launch(void* const* d_in, const int* in_sizes, int n_in,
                              void* d_out, int out_size) {
    const float* feature = (const float*)d_in[0];
    const float* rois = (const float*)d_in[1];
    int R = in_sizes[1] / 4;

    init_bins_kernel<<<1, 256>>>();

    dim3 tb(32, 8);
    dim3 tg(HWSZ / 32, CC / 64);
    transpose_kernel<<<tg, tb>>>(feature);

    int warps = R * BINS;
    int blocks = (warps + 7) / 8;
    roi_max_kernel<<<blocks, 256>>>(rois, R);

    int total4 = out_size / 4;
    bcast_kernel<<<928, 256>>>((float*)d_out, total4);
}